// round 13
// baseline (speedup 1.0000x reference)
#include <cuda_runtime.h>
#include <cstdint>

// ---------------------------------------------------------------------------
// MyModel_87522843559014: LSTM(B=256,T=512,F=128,H=256) + MLP head
//   reset -> xz -> dummy -> lstm (ncu captures 4th launch) -> head
//   xz: tf32 mma.sync GEMM (R12, 443us).
//   lstm R13: 64 blocks = 8 super-groups x 8 col-blocks. Each block runs TWO
//   independent 16-batch recurrences with the SAME weight registers,
//   interleaved so each stream's flag round-trip hides under the other's
//   compute. Split post/wait flag protocol (padded L2 flags, no atomics).
// ---------------------------------------------------------------------------

typedef unsigned long long ull;

__device__ float g_xz[512u * 256u * 1024u];   // [T][B][4H] fp32
__device__ float g_h[2][256][256];            // double-buffered hidden state
__device__ unsigned g_flag[16 * 8 * 32];      // per-(group,colblock) flags

__global__ void reset_kernel() {
    if (threadIdx.x < 128) g_flag[threadIdx.x * 32] = 0u;
}
__global__ void dummy_kernel() {}

// ---------------- split flag barrier ------------------------------------------
__device__ __forceinline__ void flag_post(int g, int jt, unsigned id) {
    __threadfence();               // publish h stores
    __syncthreads();               // all threads done
    if (threadIdx.x == 0) {
        asm volatile("st.release.gpu.global.u32 [%0], %1;"
                     :: "l"(&g_flag[(g * 8 + jt) * 32]), "r"(id) : "memory");
    }
}
__device__ __forceinline__ void flag_wait(int g, unsigned id) {
    if (threadIdx.x < 8) {
        const unsigned* f = &g_flag[(g * 8 + (int)threadIdx.x) * 32];
        unsigned v;
        do {
            asm volatile("ld.acquire.gpu.global.u32 %0, [%1];"
                         : "=r"(v) : "l"(f) : "memory");
        } while (v < id);
    }
    __syncthreads();
}

// ---------------- fast activations -------------------------------------------
__device__ __forceinline__ float sigf(float x)     { return 1.f / (1.f + __expf(-x)); }
__device__ __forceinline__ float tanhfast(float x) { return 2.f / (1.f + __expf(-2.f * x)) - 1.f; }

// ---------------- tf32 mma helpers --------------------------------------------
__device__ __forceinline__ uint32_t to_tf32(float f) {
    uint32_t u;
    asm("cvt.rna.tf32.f32 %0, %1;" : "=r"(u) : "f"(f));
    return u;
}
__device__ __forceinline__ void mma_tf32(float* c, const uint32_t* a,
                                         const uint32_t* b) {
    asm volatile(
        "mma.sync.aligned.m16n8k8.row.col.f32.tf32.tf32.f32 "
        "{%0,%1,%2,%3}, {%4,%5,%6,%7}, {%8,%9}, {%0,%1,%2,%3};"
        : "+f"(c[0]), "+f"(c[1]), "+f"(c[2]), "+f"(c[3])
        : "r"(a[0]), "r"(a[1]), "r"(a[2]), "r"(a[3]), "r"(b[0]), "r"(b[1]));
}

// ---------------- input projection GEMM (tf32 mma, single K=128 pass) ---------
#define XZ_SMEM 131072
__global__ void __launch_bounds__(256, 1)
xz_gemm_kernel(const float* __restrict__ x, const float* __restrict__ kern) {
    extern __shared__ char smx[];
    uint4* AF = (uint4*)(smx);
    uint2* BF = (uint2*)(smx + 65536);

    const int tid = threadIdx.x;
    const int wid = tid >> 5, lane = tid & 31;
    const int gid = lane >> 2, tig = lane & 3;
    const int nb = blockIdx.x;
    const int mb = blockIdx.y;
    const int m0 = mb * 128, n0 = nb * 128;

#pragma unroll
    for (int u = 0; u < 16; u++) {
        int idx = tid + u * 256;
        int l = idx & 31, t2 = idx >> 5;
        int i = t2 & 1, km = (t2 >> 1) & 15, mh = t2 >> 5;
        int g2 = l >> 2, t4 = l & 3;
        int mr0 = m0 + mh * 32 + i * 16 + g2;
        int mr1 = mr0 + 8;
        const float* xr0 = x + ((size_t)(mr0 & 255) * 512 + (mr0 >> 8)) * 128;
        const float* xr1 = x + ((size_t)(mr1 & 255) * 512 + (mr1 >> 8)) * 128;
        int k = km * 8 + t4;
        uint4 v;
        v.x = to_tf32(xr0[k]);
        v.y = to_tf32(xr1[k]);
        v.z = to_tf32(xr0[k + 4]);
        v.w = to_tf32(xr1[k + 4]);
        AF[idx] = v;
    }
#pragma unroll
    for (int u = 0; u < 32; u++) {
        int idx = tid + u * 256;
        int l = idx & 31, t2 = idx >> 5;
        int j = t2 & 7, km = (t2 >> 3) & 15, nh = t2 >> 7;
        int n = n0 + nh * 64 + j * 8 + (l >> 2);
        int k = km * 8 + (l & 3);
        uint2 v;
        v.x = to_tf32(kern[(size_t)k * 1024 + n]);
        v.y = to_tf32(kern[(size_t)(k + 4) * 1024 + n]);
        BF[idx] = v;
    }
    __syncthreads();

    const int mh = wid >> 1, nh = wid & 1;
    const uint4* afp = AF + (mh * 16) * 2 * 32 + lane;
    const uint2* bfp = BF + (nh * 16) * 8 * 32 + lane;

    float cacc[2][8][4];
#pragma unroll
    for (int i = 0; i < 2; i++)
#pragma unroll
        for (int j = 0; j < 8; j++)
#pragma unroll
            for (int r = 0; r < 4; r++) cacc[i][j][r] = 0.f;

#pragma unroll
    for (int km = 0; km < 16; km++) {
        uint32_t a[2][4];
#pragma unroll
        for (int i = 0; i < 2; i++) {
            uint4 av = afp[(km * 2 + i) * 32];
            a[i][0] = av.x; a[i][1] = av.y; a[i][2] = av.z; a[i][3] = av.w;
        }
#pragma unroll
        for (int j = 0; j < 8; j++) {
            uint2 bv = bfp[(km * 8 + j) * 32];
            uint32_t b[2] = {bv.x, bv.y};
            mma_tf32(cacc[0][j], a[0], b);
            mma_tf32(cacc[1][j], a[1], b);
        }
    }

#pragma unroll
    for (int i = 0; i < 2; i++) {
        int mr = m0 + mh * 32 + i * 16 + gid;
#pragma unroll
        for (int j = 0; j < 8; j++) {
            int nc = n0 + nh * 64 + j * 8 + tig * 2;
            *(float2*)&g_xz[(size_t)mr * 1024 + nc] =
                make_float2(cacc[i][j][0], cacc[i][j][1]);
            *(float2*)&g_xz[(size_t)(mr + 8) * 1024 + nc] =
                make_float2(cacc[i][j][2], cacc[i][j][3]);
        }
    }
}

// smem layout (bytes). AF staging (131072B) aliases loop-time regions.
#define SM_BFX   0         // stream X B fragments   16384
#define SM_BFY   16384     // stream Y B fragments   16384
#define SM_ZS    32768     // 4 x [128][17] f32      34816 (time-shared X/Y)
#define SM_CS    67584     // [1024] f32 cell state (512 per stream)  4096
#define SM_TOTAL 131072

// ---------------- persistent LSTM kernel (tf32 mma, 2-stream interleave) ------
// 64 blocks: grp2 = blockIdx>>3 (0..7), jt = blockIdx&7. Streams s=0,1 handle
// batch-groups g = 2*grp2+s (16 batches each). Block owns 128 gate-cols (M).
// Warp wid: mh=wid>>2 (M half), kq=wid&3 (K quarter). A regs shared by streams.
__global__ void __launch_bounds__(256, 1)
lstm_kernel(const float* __restrict__ rkernel) {
    extern __shared__ char smem[];
    uint4*  AF  = (uint4*)(smem);            // staging only (pre-loop)
    float*  zs  = (float*)(smem + SM_ZS);
    float*  c_s = (float*)(smem + SM_CS);

    const int tid = threadIdx.x;
    const int wid = tid >> 5, lane = tid & 31;
    const int grp2 = blockIdx.x >> 3;   // 0..7
    const int jt   = blockIdx.x & 7;    // 0..7
    const int jbase = jt * 32;
    const int gid = lane >> 2, tig = lane & 3;

    // ---- stage A fragments in smem (fragment order), then copy to registers
    for (int idx = tid; idx < 8192; idx += 256) {
        int ln = idx & 31, t2 = idx >> 5;
        int i  = t2 & 3, km = (t2 >> 2) & 7, kqz = (t2 >> 5) & 3, mhz = t2 >> 7;
        int g2 = ln >> 2, t4 = ln & 3;
        int M0 = mhz * 64 + i * 16, K0 = kqz * 64 + km * 8;
        int mr0 = M0 + g2, mr1 = M0 + 8 + g2;
        int col0 = (mr0 >> 5) * 256 + jbase + (mr0 & 31);
        int col1 = (mr1 >> 5) * 256 + jbase + (mr1 & 31);
        uint4 v;
        v.x = to_tf32(rkernel[(K0 + t4) * 1024 + col0]);
        v.y = to_tf32(rkernel[(K0 + t4) * 1024 + col1]);
        v.z = to_tf32(rkernel[(K0 + t4 + 4) * 1024 + col0]);
        v.w = to_tf32(rkernel[(K0 + t4 + 4) * 1024 + col1]);
        AF[idx] = v;
    }
    __syncthreads();

    const int mh = wid >> 2, kq = wid & 3;
    const int Mbase = mh * 64;
    uint4 areg[4][8];
    {
        const uint4* afp = AF + (mh * 4 + kq) * 1024 + lane;
#pragma unroll
        for (int i = 0; i < 4; i++)
#pragma unroll
            for (int km = 0; km < 8; km++)
                areg[i][km] = afp[km * 128 + i * 32];
    }
    __syncthreads();   // AF region now reusable

    // init: c=0 and h0 slices = 0 for both streams
#pragma unroll
    for (int s = 0; s < 2; s++) {
        int bbs = (grp2 * 2 + s) * 16;
        for (int p = tid; p < 512; p += 256) {
            int bb = p >> 5, jj = p & 31;
            c_s[s * 512 + p] = 0.f;
            g_h[0][bbs + bb][jbase + jj] = 0.f;
        }
    }
    flag_post(grp2 * 2 + 0, jt, 1u);
    flag_post(grp2 * 2 + 1, jt, 1u);

    // xz prefetch registers per stream: [s][pp*4 + gate]
    float xzp[2][8], xzn[2][8];
#pragma unroll
    for (int s = 0; s < 2; s++) {
        int bbs = (grp2 * 2 + s) * 16;
#pragma unroll
        for (int pp = 0; pp < 2; pp++) {
            int p = tid + pp * 256;
            int bb = p >> 5, jj = p & 31;
            size_t base = ((size_t)(bbs + bb)) * 1024 + jbase + jj;
#pragma unroll
            for (int g = 0; g < 4; g++)
                xzp[s][pp * 4 + g] = __ldcg(&g_xz[base + g * 256]);
        }
    }

    for (int t = 0; t < 512; t++) {
        const int par = t & 1;
#pragma unroll
        for (int s = 0; s < 2; s++) {
            const int gg = grp2 * 2 + s;
            const int bbs = gg * 16;
            uint2* BFs = (uint2*)(smem + (s ? SM_BFY : SM_BFX));
            float* cs = c_s + s * 512;

            flag_wait(gg, (unsigned)(t + 1));   // peers finished writing h(t)

            // B fragments: h_s(t) from L2, tf32, fragment order
#pragma unroll
            for (int u = 0; u < 8; u++) {
                int idx = tid + u * 256;
                int t2 = idx >> 5;
                int j = t2 & 1, km = (t2 >> 1) & 7, kqz = t2 >> 4;
                int n = j * 8 + gid;
                int k0 = kqz * 64 + km * 8 + tig;
                uint2 v;
                v.x = to_tf32(__ldcg(&g_h[par][bbs + n][k0]));
                v.y = to_tf32(__ldcg(&g_h[par][bbs + n][k0 + 4]));
                BFs[idx] = v;
            }
            __syncthreads();

            // 64 MMAs, A from registers
            float cacc[4][2][4];
#pragma unroll
            for (int i = 0; i < 4; i++)
#pragma unroll
                for (int j = 0; j < 2; j++)
#pragma unroll
                    for (int r = 0; r < 4; r++) cacc[i][j][r] = 0.f;

            const uint2* bfp = BFs + kq * 512 + lane;
#pragma unroll
            for (int km = 0; km < 8; km++) {
                uint2 bv0 = bfp[km * 64];
                uint2 bv1 = bfp[km * 64 + 32];
                uint32_t b0[2] = {bv0.x, bv0.y};
                uint32_t b1[2] = {bv1.x, bv1.y};
#pragma unroll
                for (int i = 0; i < 4; i++) {
                    uint32_t a[4] = {areg[i][km].x, areg[i][km].y,
                                     areg[i][km].z, areg[i][km].w};
                    mma_tf32(cacc[i][0], a, b0);
                    mma_tf32(cacc[i][1], a, b1);
                }
            }

            float* zq = zs + kq * (128 * 17);
#pragma unroll
            for (int i = 0; i < 4; i++) {
                int m0 = Mbase + i * 16 + gid;
#pragma unroll
                for (int j = 0; j < 2; j++) {
                    int n0 = j * 8 + tig * 2;
                    zq[m0 * 17 + n0]           = cacc[i][j][0];
                    zq[m0 * 17 + n0 + 1]       = cacc[i][j][1];
                    zq[(m0 + 8) * 17 + n0]     = cacc[i][j][2];
                    zq[(m0 + 8) * 17 + n0 + 1] = cacc[i][j][3];
                }
            }

            // prefetch next xz for this stream
            if (t < 511) {
#pragma unroll
                for (int pp = 0; pp < 2; pp++) {
                    int p = tid + pp * 256;
                    int bb = p >> 5, jj = p & 31;
                    size_t base = ((size_t)((t + 1) * 256 + bbs + bb)) * 1024
                                + jbase + jj;
#pragma unroll
                    for (int g = 0; g < 4; g++)
                        xzn[s][pp * 4 + g] = __ldcg(&g_xz[base + g * 256]);
                }
            }
            __syncthreads();

            // gates: 512 (b,j) pairs, 2 per thread
#pragma unroll
            for (int pp = 0; pp < 2; pp++) {
                int p = tid + pp * 256;
                int bb = p >> 5, jj = p & 31;
                float zi = xzp[s][pp * 4 + 0], zf = xzp[s][pp * 4 + 1];
                float zg = xzp[s][pp * 4 + 2], zo = xzp[s][pp * 4 + 3];
#pragma unroll
                for (int q = 0; q < 4; q++) {
                    const float* zb = zs + q * (128 * 17);
                    zi += zb[(jj)      * 17 + bb];
                    zf += zb[(32 + jj) * 17 + bb];
                    zg += zb[(64 + jj) * 17 + bb];
                    zo += zb[(96 + jj) * 17 + bb];
                }
                float cn = sigf(zf) * cs[p] + sigf(zi) * tanhfast(zg);
                cs[p] = cn;
                g_h[par ^ 1][bbs + bb][jbase + jj] = sigf(zo) * tanhfast(cn);
            }
#pragma unroll
            for (int r = 0; r < 8; r++) xzp[s][r] = xzn[s][r];

            if (t < 511) flag_post(gg, jt, (unsigned)(t + 2));
            else __syncthreads();   // protect zs before next stream's MMA
        }
    }
    // final h in g_h[0] (512 even); kernel boundary syncs before head
}

// ---------------- MLP head ---------------------------------------------------
__global__ void __launch_bounds__(256)
head_kernel(const float* __restrict__ w1, const float* __restrict__ b1,
            const float* __restrict__ w2, const float* __restrict__ b2,
            float* __restrict__ out) {
    __shared__ float hs[256];
    __shared__ float ys[100];
    const int b = blockIdx.x, tid = threadIdx.x;
    hs[tid] = g_h[0][b][tid];
    __syncthreads();
    if (tid < 100) {
        float a = b1[tid];
#pragma unroll 4
        for (int k = 0; k < 256; k++) a = fmaf(hs[k], w1[k * 100 + tid], a);
        ys[tid] = fmaxf(a, 0.f);
    }
    __syncthreads();
    if (tid == 0) {
        float s = b2[0];
        for (int j = 0; j < 100; j++) s = fmaf(ys[j], w2[j], s);
        out[b] = s;
    }
}

// ---------------- launch ------------------------------------------------------
extern "C" void kernel_launch(void* const* d_in, const int* in_sizes, int n_in,
                              void* d_out, int out_size) {
    const float* x    = (const float*)d_in[0];
    const float* kern = (const float*)d_in[1];
    const float* rk   = (const float*)d_in[2];
    const float* w1   = (const float*)d_in[3];
    const float* b1   = (const float*)d_in[4];
    const float* w2   = (const float*)d_in[5];
    const float* b2   = (const float*)d_in[6];
    float* out = (float*)d_out;

    cudaFuncSetAttribute(xz_gemm_kernel, cudaFuncAttributeMaxDynamicSharedMemorySize,
                         XZ_SMEM);
    cudaFuncSetAttribute(lstm_kernel, cudaFuncAttributeMaxDynamicSharedMemorySize,
                         SM_TOTAL);

    // order puts ncu's capture (4th launch of cycle) on lstm_kernel
    reset_kernel<<<1, 128>>>();
    dim3 gg(8, 1024);
    xz_gemm_kernel<<<gg, 256, XZ_SMEM>>>(x, kern);
    dummy_kernel<<<1, 1>>>();
    lstm_kernel<<<64, 256, SM_TOTAL>>>(rk);
    head_kernel<<<256, 256>>>(w1, b1, w2, b2, out);
}

// round 14
// speedup vs baseline: 1.6664x; 1.6664x over previous
#include <cuda_runtime.h>
#include <cstdint>

// ---------------------------------------------------------------------------
// MyModel_87522843559014: LSTM(B=256,T=512,F=128,H=256) + MLP head
//   reset -> xz -> dummy -> lstm (ncu captures 4th launch) -> head
//   xz: tf32 mma.sync GEMM (R12, 443us).
//   lstm R14: R12 topology (16 groups x 8 blocks, fused flag barrier) but:
//     - warp owns full K=256 and an M-tile holding all 4 gates of 4 j's
//       -> gates computed warp-locally via shfl (no zs smem, one sync/step)
//     - h exchanged as tf32 B-FRAGMENTS in global (g_hf): producer converts,
//       consumer B-fill is 4 coalesced LDG.128 + STS.128.
//     - cell state in registers.
// ---------------------------------------------------------------------------

typedef unsigned long long ull;

__device__ float g_xz[512u * 256u * 1024u];    // [T][B][4H] fp32
__device__ float g_h[256][256];                // final h (head input)
__device__ uint32_t g_hf[2][16][4096];         // h as tf32 B-fragments, 2 bufs
__device__ unsigned g_flag[16 * 8 * 32];       // per-(group,colblock) flags

__global__ void reset_kernel() {
    if (threadIdx.x < 128) g_flag[threadIdx.x * 32] = 0u;
}
__global__ void dummy_kernel() {}

// ---------------- fused flag barrier (8 blocks/group) -------------------------
__device__ __forceinline__ void flag_sync(int grp, int jt, unsigned id) {
    __threadfence();
    __syncthreads();
    if (threadIdx.x == 0) {
        asm volatile("st.release.gpu.global.u32 [%0], %1;"
                     :: "l"(&g_flag[(grp * 8 + jt) * 32]), "r"(id) : "memory");
    }
    if (threadIdx.x < 8) {
        const unsigned* f = &g_flag[(grp * 8 + (int)threadIdx.x) * 32];
        unsigned v;
        do {
            asm volatile("ld.acquire.gpu.global.u32 %0, [%1];"
                         : "=r"(v) : "l"(f) : "memory");
        } while (v < id);
    }
    __syncthreads();
}

// ---------------- fast activations -------------------------------------------
__device__ __forceinline__ float sigf(float x)     { return 1.f / (1.f + __expf(-x)); }
__device__ __forceinline__ float tanhfast(float x) { return 2.f / (1.f + __expf(-2.f * x)) - 1.f; }

// ---------------- tf32 mma helpers --------------------------------------------
__device__ __forceinline__ uint32_t to_tf32(float f) {
    uint32_t u;
    asm("cvt.rna.tf32.f32 %0, %1;" : "=r"(u) : "f"(f));
    return u;
}
__device__ __forceinline__ void mma_tf32(float* c, const uint32_t* a,
                                         const uint32_t* b) {
    asm volatile(
        "mma.sync.aligned.m16n8k8.row.col.f32.tf32.tf32.f32 "
        "{%0,%1,%2,%3}, {%4,%5,%6,%7}, {%8,%9}, {%0,%1,%2,%3};"
        : "+f"(c[0]), "+f"(c[1]), "+f"(c[2]), "+f"(c[3])
        : "r"(a[0]), "r"(a[1]), "r"(a[2]), "r"(a[3]), "r"(b[0]), "r"(b[1]));
}

// ---------------- input projection GEMM (tf32 mma, R12 unchanged) -------------
#define XZ_SMEM 131072
__global__ void __launch_bounds__(256, 1)
xz_gemm_kernel(const float* __restrict__ x, const float* __restrict__ kern) {
    extern __shared__ char smx[];
    uint4* AF = (uint4*)(smx);
    uint2* BF = (uint2*)(smx + 65536);

    const int tid = threadIdx.x;
    const int wid = tid >> 5, lane = tid & 31;
    const int gid = lane >> 2, tig = lane & 3;
    const int nb = blockIdx.x;
    const int mb = blockIdx.y;
    const int m0 = mb * 128, n0 = nb * 128;

#pragma unroll
    for (int u = 0; u < 16; u++) {
        int idx = tid + u * 256;
        int l = idx & 31, t2 = idx >> 5;
        int i = t2 & 1, km = (t2 >> 1) & 15, mh = t2 >> 5;
        int g2 = l >> 2, t4 = l & 3;
        int mr0 = m0 + mh * 32 + i * 16 + g2;
        int mr1 = mr0 + 8;
        const float* xr0 = x + ((size_t)(mr0 & 255) * 512 + (mr0 >> 8)) * 128;
        const float* xr1 = x + ((size_t)(mr1 & 255) * 512 + (mr1 >> 8)) * 128;
        int k = km * 8 + t4;
        uint4 v;
        v.x = to_tf32(xr0[k]);
        v.y = to_tf32(xr1[k]);
        v.z = to_tf32(xr0[k + 4]);
        v.w = to_tf32(xr1[k + 4]);
        AF[idx] = v;
    }
#pragma unroll
    for (int u = 0; u < 32; u++) {
        int idx = tid + u * 256;
        int l = idx & 31, t2 = idx >> 5;
        int j = t2 & 7, km = (t2 >> 3) & 15, nh = t2 >> 7;
        int n = n0 + nh * 64 + j * 8 + (l >> 2);
        int k = km * 8 + (l & 3);
        uint2 v;
        v.x = to_tf32(kern[(size_t)k * 1024 + n]);
        v.y = to_tf32(kern[(size_t)(k + 4) * 1024 + n]);
        BF[idx] = v;
    }
    __syncthreads();

    const int mh = wid >> 1, nh = wid & 1;
    const uint4* afp = AF + (mh * 16) * 2 * 32 + lane;
    const uint2* bfp = BF + (nh * 16) * 8 * 32 + lane;

    float cacc[2][8][4];
#pragma unroll
    for (int i = 0; i < 2; i++)
#pragma unroll
        for (int j = 0; j < 8; j++)
#pragma unroll
            for (int r = 0; r < 4; r++) cacc[i][j][r] = 0.f;

#pragma unroll
    for (int km = 0; km < 16; km++) {
        uint32_t a[2][4];
#pragma unroll
        for (int i = 0; i < 2; i++) {
            uint4 av = afp[(km * 2 + i) * 32];
            a[i][0] = av.x; a[i][1] = av.y; a[i][2] = av.z; a[i][3] = av.w;
        }
#pragma unroll
        for (int j = 0; j < 8; j++) {
            uint2 bv = bfp[(km * 8 + j) * 32];
            uint32_t b[2] = {bv.x, bv.y};
            mma_tf32(cacc[0][j], a[0], b);
            mma_tf32(cacc[1][j], a[1], b);
        }
    }

#pragma unroll
    for (int i = 0; i < 2; i++) {
        int mr = m0 + mh * 32 + i * 16 + gid;
#pragma unroll
        for (int j = 0; j < 8; j++) {
            int nc = n0 + nh * 64 + j * 8 + tig * 2;
            *(float2*)&g_xz[(size_t)mr * 1024 + nc] =
                make_float2(cacc[i][j][0], cacc[i][j][1]);
            *(float2*)&g_xz[(size_t)(mr + 8) * 1024 + nc] =
                make_float2(cacc[i][j][2], cacc[i][j][3]);
        }
    }
}

// smem: AF staging (131072B) aliases BF (16KB used in loop).
#define SM_TOTAL 131072

// ---------------- persistent LSTM kernel (R14) --------------------------------
// 16 groups x 8 blocks, 256 threads. Block: 16 batches (N) x 128 gate-cols (M)
// with M-row r of warp w -> rkernel column (r&3)*256 + jt*32 + w*4 + (r>>2).
// Warp: full K=256 (32 chained MMAs), 2 n-tiles. Gates via 3-round shfl.
__global__ void __launch_bounds__(256, 1)
lstm_kernel(const float* __restrict__ rkernel) {
    extern __shared__ char smem[];
    uint4* AF  = (uint4*)(smem);             // staging only (pre-loop)
    uint2* BFu2 = (uint2*)(smem);            // loop: B fragments (16KB)
    uint4* BFu4 = (uint4*)(smem);

    const int tid = threadIdx.x;
    const int wid = tid >> 5, lane = tid & 31;
    const int grp = blockIdx.x >> 3;    // 0..15
    const int jt  = blockIdx.x & 7;     // 0..7
    const int bbase = grp * 16, jbase = jt * 32;
    const int gid = lane >> 2, tig = lane & 3;
    const int g   = gid & 3;            // gate owned by this lane's m-rows
    const int jl  = gid >> 2;           // j-offset low bit

    // ---- stage A fragments (new col mapping), copy to registers
    for (int idx = tid; idx < 8192; idx += 256) {
        int l = idx & 31, t2 = idx >> 5;
        int km = t2 & 31, w = t2 >> 5;
        int g2 = l >> 2, t4 = l & 3;
        // col(r) = (r&3)*256 + jbase + w*4 + (r>>2); col(g2+8) = col(g2)+2
        int col0 = (g2 & 3) * 256 + jbase + w * 4 + (g2 >> 2);
        int col1 = col0 + 2;
        int k = km * 8 + t4;
        uint4 v;
        v.x = to_tf32(rkernel[(size_t)k * 1024 + col0]);
        v.y = to_tf32(rkernel[(size_t)k * 1024 + col1]);
        v.z = to_tf32(rkernel[(size_t)(k + 4) * 1024 + col0]);
        v.w = to_tf32(rkernel[(size_t)(k + 4) * 1024 + col1]);
        AF[idx] = v;
    }
    __syncthreads();

    uint4 areg[32];
    {
        const uint4* afp = AF + wid * 32 * 32 + lane;
#pragma unroll
        for (int km = 0; km < 32; km++) areg[km] = afp[km * 32];
    }
    __syncthreads();   // AF region now reusable as BF

    // zero h0 fragment buffer (par=0) slice
    for (int i = tid; i < 512; i += 256)
        g_hf[0][grp][jt * 512 + i] = 0u;
    flag_sync(grp, jt, 1u);

    // per-lane constants
    const int kcol = jbase + wid * 4 + jl + (g & 1) * 2;  // hidden idx of my slot
    const int n0   = (g >> 1) * 8 + tig * 2;              // batches n0, n0+1
    // fragment offset e(n0, kcol)
    const int e0 = ((kcol >> 3) * 2 + (n0 >> 3)) * 64 + (n0 & 7) * 8
                 + (kcol & 3) * 2 + ((kcol >> 2) & 1);
    // xz offsets for my 8 cacc slots: [nt][ci]; colA for rows gid, colA+2 rows gid+8
    const int colA = (gid & 3) * 256 + jbase + wid * 4 + (gid >> 2);
    int xoff[2][4];
#pragma unroll
    for (int nt = 0; nt < 2; nt++) {
        int nn = nt * 8 + tig * 2;
        xoff[nt][0] = (bbase + nn) * 1024 + colA;
        xoff[nt][1] = (bbase + nn + 1) * 1024 + colA;
        xoff[nt][2] = (bbase + nn) * 1024 + colA + 2;
        xoff[nt][3] = (bbase + nn + 1) * 1024 + colA + 2;
    }

    float cr0 = 0.f, cr1 = 0.f;   // cell state for my 2 (b,j) pairs
    float xzp[2][4], xzn[2][4];
#pragma unroll
    for (int nt = 0; nt < 2; nt++)
#pragma unroll
        for (int ci = 0; ci < 4; ci++)
            xzp[nt][ci] = __ldcg(&g_xz[xoff[nt][ci]]);

    for (int t = 0; t < 512; t++) {
        const int par = t & 1;

        // B-fill: coalesced copy of tf32 fragments
        const uint4* src = (const uint4*)&g_hf[par][grp][0];
#pragma unroll
        for (int u = 0; u < 4; u++) {
            int idx = tid + u * 256;
            uint4 v;
            asm volatile("ld.global.cg.v4.u32 {%0,%1,%2,%3}, [%4];"
                         : "=r"(v.x), "=r"(v.y), "=r"(v.z), "=r"(v.w)
                         : "l"(src + idx));
            BFu4[idx] = v;
        }
        __syncthreads();

        // 64 MMAs: 32 km x 2 n-tiles, A from registers
        float cacc[2][4];
#pragma unroll
        for (int nt = 0; nt < 2; nt++)
#pragma unroll
            for (int r = 0; r < 4; r++) cacc[nt][r] = 0.f;

        const uint2* bfp = BFu2 + lane;
#pragma unroll
        for (int km = 0; km < 32; km++) {
            uint32_t a[4] = {areg[km].x, areg[km].y, areg[km].z, areg[km].w};
            uint2 bv0 = bfp[(km * 2) * 32];
            uint2 bv1 = bfp[(km * 2 + 1) * 32];
            uint32_t b0[2] = {bv0.x, bv0.y};
            uint32_t b1[2] = {bv1.x, bv1.y};
            mma_tf32(cacc[0], a, b0);
            mma_tf32(cacc[1], a, b1);
        }

        // add xz (own slots), prefetch next xz
#pragma unroll
        for (int nt = 0; nt < 2; nt++)
#pragma unroll
            for (int ci = 0; ci < 4; ci++) cacc[nt][ci] += xzp[nt][ci];
        if (t < 511) {
            size_t tb = (size_t)(t + 1) * 256 * 1024;
#pragma unroll
            for (int nt = 0; nt < 2; nt++)
#pragma unroll
                for (int ci = 0; ci < 4; ci++)
                    xzn[nt][ci] = __ldcg(&g_xz[tb + xoff[nt][ci]]);
        }

        // shfl exchange: slot s values = cacc[s>>1][(s&1)*2 + v]
        float own0, own1, r10, r11, r20, r21, r30, r31;
        own0 = (g == 0) ? cacc[0][0] : (g == 1) ? cacc[0][2]
             : (g == 2) ? cacc[1][0] : cacc[1][2];
        own1 = (g == 0) ? cacc[0][1] : (g == 1) ? cacc[0][3]
             : (g == 2) ? cacc[1][1] : cacc[1][3];
#pragma unroll
        for (int k = 1; k <= 3; k++) {
            int s = g ^ k;
            float t0 = (s == 0) ? cacc[0][0] : (s == 1) ? cacc[0][2]
                     : (s == 2) ? cacc[1][0] : cacc[1][2];
            float t1 = (s == 0) ? cacc[0][1] : (s == 1) ? cacc[0][3]
                     : (s == 2) ? cacc[1][1] : cacc[1][3];
            int srcl = (lane & 0x13) | (s << 2);
            float q0 = __shfl_sync(0xffffffffu, t0, srcl);
            float q1 = __shfl_sync(0xffffffffu, t1, srcl);
            if (k == 1) { r10 = q0; r11 = q1; }
            else if (k == 2) { r20 = q0; r21 = q1; }
            else { r30 = q0; r31 = q1; }
        }
        // z by gate q: kk = g^q selects own/round
        float zq0[4], zq1[4];
#pragma unroll
        for (int q = 0; q < 4; q++) {
            int kk = g ^ q;
            zq0[q] = (kk == 0) ? own0 : (kk == 1) ? r10 : (kk == 2) ? r20 : r30;
            zq1[q] = (kk == 0) ? own1 : (kk == 1) ? r11 : (kk == 2) ? r21 : r31;
        }

        // gates for 2 pairs: (b = bbase+n0, j = kcol) and (b+1, j)
        float cn0 = sigf(zq0[1]) * cr0 + sigf(zq0[0]) * tanhfast(zq0[2]);
        float cn1 = sigf(zq1[1]) * cr1 + sigf(zq1[0]) * tanhfast(zq1[2]);
        cr0 = cn0; cr1 = cn1;
        float h0 = sigf(zq0[3]) * tanhfast(cn0);
        float h1 = sigf(zq1[3]) * tanhfast(cn1);

        if (t < 511) {
            uint32_t* dst = &g_hf[par ^ 1][grp][0];
            dst[e0]     = to_tf32(h0);
            dst[e0 + 8] = to_tf32(h1);
        } else {
            g_h[bbase + n0][kcol]     = h0;
            g_h[bbase + n0 + 1][kcol] = h1;
        }
#pragma unroll
        for (int nt = 0; nt < 2; nt++)
#pragma unroll
            for (int ci = 0; ci < 4; ci++) xzp[nt][ci] = xzn[nt][ci];

        if (t < 511) flag_sync(grp, jt, (unsigned)(t + 2));
    }
    // kernel boundary syncs before head
}

// ---------------- MLP head ---------------------------------------------------
__global__ void __launch_bounds__(256)
head_kernel(const float* __restrict__ w1, const float* __restrict__ b1,
            const float* __restrict__ w2, const float* __restrict__ b2,
            float* __restrict__ out) {
    __shared__ float hs[256];
    __shared__ float ys[100];
    const int b = blockIdx.x, tid = threadIdx.x;
    hs[tid] = g_h[b][tid];
    __syncthreads();
    if (tid < 100) {
        float a = b1[tid];
#pragma unroll 4
        for (int k = 0; k < 256; k++) a = fmaf(hs[k], w1[k * 100 + tid], a);
        ys[tid] = fmaxf(a, 0.f);
    }
    __syncthreads();
    if (tid == 0) {
        float s = b2[0];
        for (int j = 0; j < 100; j++) s = fmaf(ys[j], w2[j], s);
        out[b] = s;
    }
}

// ---------------- launch ------------------------------------------------------
extern "C" void kernel_launch(void* const* d_in, const int* in_sizes, int n_in,
                              void* d_out, int out_size) {
    const float* x    = (const float*)d_in[0];
    const float* kern = (const float*)d_in[1];
    const float* rk   = (const float*)d_in[2];
    const float* w1   = (const float*)d_in[3];
    const float* b1   = (const float*)d_in[4];
    const float* w2   = (const float*)d_in[5];
    const float* b2   = (const float*)d_in[6];
    float* out = (float*)d_out;

    cudaFuncSetAttribute(xz_gemm_kernel, cudaFuncAttributeMaxDynamicSharedMemorySize,
                         XZ_SMEM);
    cudaFuncSetAttribute(lstm_kernel, cudaFuncAttributeMaxDynamicSharedMemorySize,
                         SM_TOTAL);

    // order puts ncu's capture (4th launch of cycle) on lstm_kernel
    reset_kernel<<<1, 128>>>();
    dim3 gg(8, 1024);
    xz_gemm_kernel<<<gg, 256, XZ_SMEM>>>(x, kern);
    dummy_kernel<<<1, 1>>>();
    lstm_kernel<<<128, 256, SM_TOTAL>>>(rk);
    head_kernel<<<256, 256>>>(w1, b1, w2, b2, out);
}